// round 12
// baseline (speedup 1.0000x reference)
#include <cuda_runtime.h>
#include <cuda_fp16.h>
#include <cstdint>

#define NE 800000
#define NN 50000
#define NTILES (NE/128)
#define RSQ2 0.70710678118654752440f

__device__ float g_h[NN * 64];
__device__ int   g_mask_mode;

// ---------------- helpers ----------------
static __device__ __forceinline__ uint32_t s2u(const void* p) {
    uint32_t a;
    asm("{ .reg .u64 t; cvta.to.shared.u64 t, %1; cvt.u32.u64 %0, t; }" : "=r"(a) : "l"(p));
    return a;
}
static __device__ __forceinline__ void ldsm4(uint32_t a, uint32_t r[4]) {
    asm volatile("ldmatrix.sync.aligned.m8n8.x4.shared.b16 {%0,%1,%2,%3}, [%4];"
                 : "=r"(r[0]), "=r"(r[1]), "=r"(r[2]), "=r"(r[3]) : "r"(a));
}
static __device__ __forceinline__ void ldsm2(uint32_t a, uint32_t r[2]) {
    asm volatile("ldmatrix.sync.aligned.m8n8.x2.shared.b16 {%0,%1}, [%2];"
                 : "=r"(r[0]), "=r"(r[1]) : "r"(a));
}
static __device__ __forceinline__ void mma16816(float c[4], const uint32_t a[4],
                                                const uint32_t b[2]) {
    asm volatile("mma.sync.aligned.m16n8k16.row.col.f32.f16.f16.f32 "
                 "{%0,%1,%2,%3}, {%4,%5,%6,%7}, {%8,%9}, {%0,%1,%2,%3};"
                 : "+f"(c[0]), "+f"(c[1]), "+f"(c[2]), "+f"(c[3])
                 : "r"(a[0]), "r"(a[1]), "r"(a[2]), "r"(a[3]), "r"(b[0]), "r"(b[1]));
}
static __device__ __forceinline__ void red4(float* p, float a, float b, float c, float d) {
    asm volatile("red.global.add.v4.f32 [%0], {%1, %2, %3, %4};"
                 :: "l"(p), "f"(a), "f"(b), "f"(c), "f"(d) : "memory");
}
static __device__ __forceinline__ uint32_t f2h2(float a, float b) {
    __half2 h = __floats2half2_rn(a, b);
    return *(uint32_t*)&h;
}
static __device__ __forceinline__ void cvt8h(const float* x, uint4& o) {
    o = make_uint4(f2h2(x[0], x[1]), f2h2(x[2], x[3]),
                   f2h2(x[4], x[5]), f2h2(x[6], x[7]));
}

// ---------------- mask dtype ----------------
static __device__ __forceinline__ bool get_mask(const void* m, int e, int mode) {
    if (mode == 0) return ((const int*)m)[e] != 0;
    if (mode == 1) return ((const unsigned char*)m)[e] != 0;
    return ((const float*)m)[e] != 0.0f;
}
__global__ void probe_mask_kernel(const unsigned char* __restrict__ m) {
    __shared__ int flag[4];
    int t = threadIdx.x;
    if (t < 4) flag[t] = 0;
    __syncthreads();
    int any = 0;
    for (int i = t; i < 4096; i += 256) any |= (int)m[i];
    if (any) atomicOr(&flag[t & 3], 1);
    __syncthreads();
    if (t == 0) {
        int mode;
        if (flag[1] || (flag[0] && (flag[2] | flag[3]))) mode = 1;   // u8/bool
        else if (flag[2] | flag[3])                      mode = 2;   // f32
        else                                             mode = 0;   // i32
        g_mask_mode = mode;
    }
}

__global__ void zero_h_kernel() {
    float4* p = (float4*)g_h;
    const int n = NN * 64 / 4;
    for (int i = blockIdx.x * blockDim.x + threadIdx.x; i < n; i += gridDim.x * blockDim.x)
        p[i] = make_float4(0.f, 0.f, 0.f, 0.f);
}

// ---------------- scatter: z = (attr @ W_in^T)*dinv ; phase*z -> g_h ----------------
// smem: W[64][136]h, A[128][136]h, coef f4[128], u[128], v[128]
// warp w: wm = w>>2 (M half, 64 rows = 4 mt), wn = w&3 (16-col group, 2 strips)
#define SC_W  0
#define SC_A  17408
#define SC_CF 52224
#define SC_U  54272
#define SC_V  54784
#define SC_SMEM 55296

__global__ __launch_bounds__(256, 3)
void scatter_kernel(const int* __restrict__ ei, const void* __restrict__ mask,
                    const float* __restrict__ attr, const float* __restrict__ W_in) {
    extern __shared__ char sm[];
    const uint32_t sb = s2u(sm);
    const int t = threadIdx.x, w = t >> 5, lane = t & 31;
    const int wm = w >> 2, wn = w & 3;
    const int mode = g_mask_mode;

    // stage W_in [64 x 128] once (fp16, padded rows of 136 halves)
    for (int g = t; g < 1024; g += 256) {
        int row = g >> 4, k0 = (g & 15) * 8;
        float x[8];
        *(float4*)&x[0] = *(const float4*)(W_in + row * 128 + k0);
        *(float4*)&x[4] = *(const float4*)(W_in + row * 128 + k0 + 4);
        uint4 hv; cvt8h(x, hv);
        *(uint4*)(sm + SC_W + (row * 136 + k0) * 2) = hv;
    }
    __syncthreads();

    // resident B fragments: warp owns hid cols [16wn, 16wn+16) -> 2 strips
    uint32_t bh[2][8][2];
    #pragma unroll
    for (int s = 0; s < 2; s++) {
        uint32_t ro = (uint32_t)(16 * wn + 8 * s + (lane & 7)) * 272;
        #pragma unroll
        for (int ks = 0; ks < 8; ks++) {
            uint32_t co = (uint32_t)(ks * 16 + (lane & 8)) * 2;
            ldsm2(sb + SC_W + ro + co, bh[s][ks]);
        }
    }
    float4* coef_s = (float4*)(sm + SC_CF);
    int*    u_s    = (int*)(sm + SC_U);
    int*    v_s    = (int*)(sm + SC_V);

    const int g4 = lane >> 2, t4 = lane & 3;

    for (int tile = blockIdx.x; tile < NTILES; tile += gridDim.x) {
        __syncthreads();
        const int eb = tile * 128;
        if (t < 128) {
            int e = eb + t;
            int u = ei[e], v = ei[NE + e];
            bool und = get_mask(mask, e, mode);
            float chr, chi, ctr, cti, dinv;
            if (und) { chr = 1.f;  chi = 0.f;   ctr = -1.f;  cti = 0.f;
                       dinv = (u == v) ? 0.f : RSQ2; }
            else     { chr = RSQ2; chi = -RSQ2; ctr = -RSQ2; cti = -RSQ2; dinv = RSQ2; }
            u_s[t] = u; v_s[t] = v;
            coef_s[t] = make_float4(dinv * chr, dinv * chi, dinv * ctr, dinv * cti);
        }
        for (int g = t; g < 2048; g += 256) {           // A tile (fp16)
            int row = g >> 4, k0 = (g & 15) * 8;
            float x[8];
            const float* ap = attr + (size_t)(eb + row) * 128 + k0;
            *(float4*)&x[0] = *(const float4*)ap;
            *(float4*)&x[4] = *(const float4*)(ap + 4);
            uint4 av; cvt8h(x, av);
            *(uint4*)(sm + SC_A + (row * 136 + k0) * 2) = av;
        }
        __syncthreads();

        // 4 mt interleaved: 8 independent accumulator chains
        float c[4][2][4];
        #pragma unroll
        for (int mt = 0; mt < 4; mt++)
            #pragma unroll
            for (int s = 0; s < 2; s++)
                c[mt][s][0] = c[mt][s][1] = c[mt][s][2] = c[mt][s][3] = 0.f;

        uint32_t acol0 = (uint32_t)((lane >> 4) << 4);
        #pragma unroll
        for (int ks = 0; ks < 8; ks++) {
            uint32_t a4[4][4];
            #pragma unroll
            for (int mt = 0; mt < 4; mt++) {
                uint32_t arow = (uint32_t)(wm * 64 + mt * 16 + (lane & 15)) * 272;
                ldsm4(sb + SC_A + arow + ks * 32 + acol0, a4[mt]);
            }
            #pragma unroll
            for (int mt = 0; mt < 4; mt++) {
                mma16816(c[mt][0], a4[mt], bh[0][ks]);
                mma16816(c[mt][1], a4[mt], bh[1][ks]);
            }
        }

        #pragma unroll
        for (int mt = 0; mt < 4; mt++) {
            #pragma unroll
            for (int s = 0; s < 2; s++) {
                int col = 16 * wn + 8 * s + 2 * t4;
                #pragma unroll
                for (int rr = 0; rr < 2; rr++) {
                    int el = wm * 64 + mt * 16 + g4 + rr * 8;
                    float re = c[mt][s][rr * 2], im = c[mt][s][rr * 2 + 1];
                    float4 cf = coef_s[el];
                    int u = u_s[el], v = v_s[el];
                    float hvx = cf.x * re - cf.y * im, hvy = cf.x * im + cf.y * re;
                    float hux = cf.z * re - cf.w * im, huy = cf.z * im + cf.w * re;
                    float pvx = __shfl_xor_sync(0xffffffffu, hvx, 1);
                    float pvy = __shfl_xor_sync(0xffffffffu, hvy, 1);
                    float pux = __shfl_xor_sync(0xffffffffu, hux, 1);
                    float puy = __shfl_xor_sync(0xffffffffu, huy, 1);
                    if (t4 & 1) red4(&g_h[(size_t)u * 64 + col - 2], pux, puy, hux, huy);
                    else        red4(&g_h[(size_t)v * 64 + col],     hvx, hvy, pvx, pvy);
                }
            }
        }
    }
}

// ---------------- gather: y = dinv*(conj-phase . relu(h)) ; out = [y|attr]@Wcat^T + b ----------------
// smem: W[128][200]h (reused as A1 after B-frag load), A0[128][200]h, bias[128]f
// 512 threads, 1 CTA/SM; warp w: wm = w>>3 (M half = 4 mt), wn = w&7 (16-col group)
#define GA_W  0
#define GA_A0 51200
#define GA_BI 102400
#define GA_SMEM 102912

__global__ __launch_bounds__(512, 1)
void gather_kernel(const int* __restrict__ ei, const void* __restrict__ mask,
                   const float* __restrict__ attr,
                   const float* __restrict__ W_out, const float* __restrict__ W_skip,
                   const float* __restrict__ b_skip, const float* __restrict__ bias,
                   float* __restrict__ out) {
    extern __shared__ char sm[];
    const uint32_t sb = s2u(sm);
    const int t = threadIdx.x, w = t >> 5, lane = t & 31;
    const int wm = w >> 3, wn = w & 7;
    const int mode = g_mask_mode;

    // stage Wcat [128 x 192] once: k<64 -> W_out, else W_skip (fp16)
    for (int g = t; g < 3072; g += 512) {
        int row = g / 24, k0 = (g % 24) * 8;
        float x[8];
        if (k0 < 64) {
            *(float4*)&x[0] = *(const float4*)(W_out + row * 64 + k0);
            *(float4*)&x[4] = *(const float4*)(W_out + row * 64 + k0 + 4);
        } else {
            *(float4*)&x[0] = *(const float4*)(W_skip + row * 128 + (k0 - 64));
            *(float4*)&x[4] = *(const float4*)(W_skip + row * 128 + (k0 - 64) + 4);
        }
        uint4 hv; cvt8h(x, hv);
        *(uint4*)(sm + GA_W + (row * 200 + k0) * 2) = hv;
    }
    if (t < 128) ((float*)(sm + GA_BI))[t] = b_skip[t] + bias[t];
    __syncthreads();

    // resident B fragments: warp owns out cols [16wn, 16wn+16) -> 2 strips
    uint32_t bh[2][12][2];
    #pragma unroll
    for (int s = 0; s < 2; s++) {
        uint32_t ro = (uint32_t)(16 * wn + 8 * s + (lane & 7)) * 400;
        #pragma unroll
        for (int ks = 0; ks < 12; ks++) {
            uint32_t co = (uint32_t)(ks * 16 + (lane & 8)) * 2;
            ldsm2(sb + GA_W + ro + co, bh[s][ks]);
        }
    }
    const int g4 = lane >> 2, t4 = lane & 3;
    float2 b2[2];
    b2[0] = *(float2*)(sm + GA_BI + (16 * wn + 2 * t4) * 4);
    b2[1] = *(float2*)(sm + GA_BI + (16 * wn + 8 + 2 * t4) * 4);
    __syncthreads();   // B frags read -> W region reusable as A1

    const uint32_t abuf[2] = { sb + GA_A0, sb + GA_W };

    // ---- stage one tile into buffer (no internal sync needed) ----
    auto stage = [&](int tile, int bi) {
        const int eb = tile * 128;
        char* buf = sm + (bi ? GA_W : GA_A0);
        for (int g = t; g < 2048; g += 512) {           // attr -> k rows [64,192)
            int row = g >> 4, k0 = (g & 15) * 8;
            float x[8];
            const float* ap = attr + (size_t)(eb + row) * 128 + k0;
            *(float4*)&x[0] = *(const float4*)ap;
            *(float4*)&x[4] = *(const float4*)(ap + 4);
            uint4 av; cvt8h(x, av);
            *(uint4*)(buf + (row * 200 + 64 + k0) * 2) = av;
        }
        for (int g = t; g < 4096; g += 512) {           // y -> k rows [0,64)
            int e = g >> 5, p = g & 31;                  // e warp-uniform
            int eg = eb + e;
            int u = ei[eg], v = ei[NE + eg];             // broadcast loads
            bool und = get_mask(mask, eg, mode);
            float ar, ai, br, bi2, dinv = RSQ2;
            if (und) { ar = 1.f;  ai = 0.f;  br = -1.f;  bi2 = 0.f;
                       if (u == v) dinv = 0.f; }
            else     { ar = RSQ2; ai = RSQ2; br = -RSQ2; bi2 = RSQ2; }
            ar *= dinv; ai *= dinv; br *= dinv; bi2 *= dinv;
            float2 hv = *(const float2*)&g_h[(size_t)v * 64 + 2 * p];
            float2 hu = *(const float2*)&g_h[(size_t)u * 64 + 2 * p];
            hv.x = fmaxf(hv.x, 0.f); hv.y = fmaxf(hv.y, 0.f);  // fused ReLU
            hu.x = fmaxf(hu.x, 0.f); hu.y = fmaxf(hu.y, 0.f);
            float yr = ar * hv.x - ai * hv.y + br * hu.x - bi2 * hu.y;
            float yi = ar * hv.y + ai * hv.x + br * hu.y + bi2 * hu.x;
            *(uint32_t*)(buf + e * 400 + 4 * p) = f2h2(yr, yi);
        }
    };

    int tile = blockIdx.x;
    if (tile < NTILES) stage(tile, 0);
    __syncthreads();
    int ph = 0;
    for (; tile < NTILES; tile += gridDim.x) {
        int next = tile + gridDim.x;
        if (next < NTILES) stage(next, ph ^ 1);          // overlap with MMA below

        const int eb = tile * 128;
        // 4 mt interleaved: 8 independent accumulator chains
        float c[4][2][4];
        #pragma unroll
        for (int mt = 0; mt < 4; mt++)
            #pragma unroll
            for (int s = 0; s < 2; s++)
                c[mt][s][0] = c[mt][s][1] = c[mt][s][2] = c[mt][s][3] = 0.f;

        uint32_t acol0 = (uint32_t)((lane >> 4) << 4);
        #pragma unroll
        for (int ks = 0; ks < 12; ks++) {
            uint32_t a4[4][4];
            #pragma unroll
            for (int mt = 0; mt < 4; mt++) {
                uint32_t arow = (uint32_t)(wm * 64 + mt * 16 + (lane & 15)) * 400;
                ldsm4(abuf[ph] + arow + ks * 32 + acol0, a4[mt]);
            }
            #pragma unroll
            for (int mt = 0; mt < 4; mt++) {
                mma16816(c[mt][0], a4[mt], bh[0][ks]);
                mma16816(c[mt][1], a4[mt], bh[1][ks]);
            }
        }

        #pragma unroll
        for (int mt = 0; mt < 4; mt++) {
            int e0 = eb + wm * 64 + mt * 16 + g4;
            #pragma unroll
            for (int s = 0; s < 2; s++) {
                int ca = 16 * wn + 8 * s + 2 * t4;
                *(float2*)&out[(size_t)e0 * 128 + ca] =
                    make_float2(c[mt][s][0] + b2[s].x, c[mt][s][1] + b2[s].y);
                *(float2*)&out[(size_t)(e0 + 8) * 128 + ca] =
                    make_float2(c[mt][s][2] + b2[s].x, c[mt][s][3] + b2[s].y);
            }
        }
        __syncthreads();
        ph ^= 1;
    }
}

extern "C" void kernel_launch(void* const* d_in, const int* in_sizes, int n_in,
                              void* d_out, int out_size) {
    const int*   edge_index = (const int*)  d_in[0];
    const void*  mask       =               d_in[1];
    const float* edge_attr  = (const float*)d_in[2];
    const float* W_in       = (const float*)d_in[3];
    const float* W_out      = (const float*)d_in[4];
    const float* W_skip     = (const float*)d_in[5];
    const float* b_skip     = (const float*)d_in[6];
    const float* bias       = (const float*)d_in[7];
    float*       out        = (float*)d_out;

    cudaFuncSetAttribute(scatter_kernel, cudaFuncAttributeMaxDynamicSharedMemorySize, SC_SMEM);
    cudaFuncSetAttribute(gather_kernel,  cudaFuncAttributeMaxDynamicSharedMemorySize, GA_SMEM);

    probe_mask_kernel<<<1, 256>>>((const unsigned char*)mask);
    zero_h_kernel<<<148, 256>>>();
    scatter_kernel<<<444, 256, SC_SMEM>>>(edge_index, mask, edge_attr, W_in);
    gather_kernel<<<148, 512, GA_SMEM>>>(edge_index, mask, edge_attr,
                                         W_out, W_skip, b_skip, bias, out);
}

// round 14
// speedup vs baseline: 1.1707x; 1.1707x over previous
#include <cuda_runtime.h>
#include <cuda_fp16.h>
#include <cstdint>

#define NE 800000
#define NN 50000
#define NTILES (NE/128)
#define RSQ2 0.70710678118654752440f

__device__ float    g_h[NN * 64];
__device__ uint32_t g_y[NE * 32];     // per-edge y, fp16x2 pairs (channels 2p,2p+1)
__device__ int      g_mask_mode;

// ---------------- helpers ----------------
static __device__ __forceinline__ uint32_t s2u(const void* p) {
    uint32_t a;
    asm("{ .reg .u64 t; cvta.to.shared.u64 t, %1; cvt.u32.u64 %0, t; }" : "=r"(a) : "l"(p));
    return a;
}
static __device__ __forceinline__ void ldsm4(uint32_t a, uint32_t r[4]) {
    asm volatile("ldmatrix.sync.aligned.m8n8.x4.shared.b16 {%0,%1,%2,%3}, [%4];"
                 : "=r"(r[0]), "=r"(r[1]), "=r"(r[2]), "=r"(r[3]) : "r"(a));
}
static __device__ __forceinline__ void ldsm2(uint32_t a, uint32_t r[2]) {
    asm volatile("ldmatrix.sync.aligned.m8n8.x2.shared.b16 {%0,%1}, [%2];"
                 : "=r"(r[0]), "=r"(r[1]) : "r"(a));
}
static __device__ __forceinline__ void mma16816(float c[4], const uint32_t a[4],
                                                const uint32_t b[2]) {
    asm volatile("mma.sync.aligned.m16n8k16.row.col.f32.f16.f16.f32 "
                 "{%0,%1,%2,%3}, {%4,%5,%6,%7}, {%8,%9}, {%0,%1,%2,%3};"
                 : "+f"(c[0]), "+f"(c[1]), "+f"(c[2]), "+f"(c[3])
                 : "r"(a[0]), "r"(a[1]), "r"(a[2]), "r"(a[3]), "r"(b[0]), "r"(b[1]));
}
static __device__ __forceinline__ void red4(float* p, float a, float b, float c, float d) {
    asm volatile("red.global.add.v4.f32 [%0], {%1, %2, %3, %4};"
                 :: "l"(p), "f"(a), "f"(b), "f"(c), "f"(d) : "memory");
}
static __device__ __forceinline__ uint32_t f2h2(float a, float b) {
    __half2 h = __floats2half2_rn(a, b);
    return *(uint32_t*)&h;
}
static __device__ __forceinline__ void cvt8h(const float* x, uint4& o) {
    o = make_uint4(f2h2(x[0], x[1]), f2h2(x[2], x[3]),
                   f2h2(x[4], x[5]), f2h2(x[6], x[7]));
}

// ---------------- mask dtype ----------------
static __device__ __forceinline__ bool get_mask(const void* m, int e, int mode) {
    if (mode == 0) return ((const int*)m)[e] != 0;
    if (mode == 1) return ((const unsigned char*)m)[e] != 0;
    return ((const float*)m)[e] != 0.0f;
}
__global__ void probe_mask_kernel(const unsigned char* __restrict__ m) {
    __shared__ int flag[4];
    int t = threadIdx.x;
    if (t < 4) flag[t] = 0;
    __syncthreads();
    int any = 0;
    for (int i = t; i < 4096; i += 256) any |= (int)m[i];
    if (any) atomicOr(&flag[t & 3], 1);
    __syncthreads();
    if (t == 0) {
        int mode;
        if (flag[1] || (flag[0] && (flag[2] | flag[3]))) mode = 1;   // u8/bool
        else if (flag[2] | flag[3])                      mode = 2;   // f32
        else                                             mode = 0;   // i32
        g_mask_mode = mode;
    }
}

__global__ void zero_h_kernel() {
    float4* p = (float4*)g_h;
    const int n = NN * 64 / 4;
    for (int i = blockIdx.x * blockDim.x + threadIdx.x; i < n; i += gridDim.x * blockDim.x)
        p[i] = make_float4(0.f, 0.f, 0.f, 0.f);
}

// ---------------- y-build: y = dinv*(conj-phase . relu(h)) -> g_y (fp16) ----------------
// warp per edge: lane = channel pair p; runs at max occupancy, L2 latency hidden.
__global__ __launch_bounds__(256)
void ybuild_kernel(const int* __restrict__ ei, const void* __restrict__ mask) {
    const int lane = threadIdx.x & 31;
    const int w    = (blockIdx.x * blockDim.x + threadIdx.x) >> 5;
    const int nw   = (gridDim.x * blockDim.x) >> 5;
    const int mode = g_mask_mode;
    for (int e = w; e < NE; e += nw) {
        int u = ei[e], v = ei[NE + e];                  // broadcast loads
        bool und = get_mask(mask, e, mode);
        float ar, ai, br, bi2, dinv = RSQ2;
        if (und) { ar = 1.f;  ai = 0.f;  br = -1.f;  bi2 = 0.f;
                   if (u == v) dinv = 0.f; }
        else     { ar = RSQ2; ai = RSQ2; br = -RSQ2; bi2 = RSQ2; }
        ar *= dinv; ai *= dinv; br *= dinv; bi2 *= dinv;
        float2 hv = *(const float2*)&g_h[(size_t)v * 64 + 2 * lane];
        float2 hu = *(const float2*)&g_h[(size_t)u * 64 + 2 * lane];
        hv.x = fmaxf(hv.x, 0.f); hv.y = fmaxf(hv.y, 0.f);  // fused ReLU
        hu.x = fmaxf(hu.x, 0.f); hu.y = fmaxf(hu.y, 0.f);
        float yr = ar * hv.x - ai * hv.y + br * hu.x - bi2 * hu.y;
        float yi = ar * hv.y + ai * hv.x + br * hu.y + bi2 * hu.x;
        g_y[(size_t)e * 32 + lane] = f2h2(yr, yi);
    }
}

// ---------------- scatter: z = (attr @ W_in^T)*dinv ; phase*z -> g_h ----------------
// smem: W[64][136]h, A[128][136]h, coef f4[128], u[128], v[128]
// warp w: wm = w>>2 (M half, 64 rows = 4 mt), wn = w&3 (16-col group, 2 strips)
#define SC_W  0
#define SC_A  17408
#define SC_CF 52224
#define SC_U  54272
#define SC_V  54784
#define SC_SMEM 55296

__global__ __launch_bounds__(256, 3)
void scatter_kernel(const int* __restrict__ ei, const void* __restrict__ mask,
                    const float* __restrict__ attr, const float* __restrict__ W_in) {
    extern __shared__ char sm[];
    const uint32_t sb = s2u(sm);
    const int t = threadIdx.x, w = t >> 5, lane = t & 31;
    const int wm = w >> 2, wn = w & 3;
    const int mode = g_mask_mode;

    // stage W_in [64 x 128] once (fp16, padded rows of 136 halves)
    for (int g = t; g < 1024; g += 256) {
        int row = g >> 4, k0 = (g & 15) * 8;
        float x[8];
        *(float4*)&x[0] = *(const float4*)(W_in + row * 128 + k0);
        *(float4*)&x[4] = *(const float4*)(W_in + row * 128 + k0 + 4);
        uint4 hv; cvt8h(x, hv);
        *(uint4*)(sm + SC_W + (row * 136 + k0) * 2) = hv;
    }
    __syncthreads();

    // resident B fragments: warp owns hid cols [16wn, 16wn+16) -> 2 strips
    uint32_t bh[2][8][2];
    #pragma unroll
    for (int s = 0; s < 2; s++) {
        uint32_t ro = (uint32_t)(16 * wn + 8 * s + (lane & 7)) * 272;
        #pragma unroll
        for (int ks = 0; ks < 8; ks++) {
            uint32_t co = (uint32_t)(ks * 16 + (lane & 8)) * 2;
            ldsm2(sb + SC_W + ro + co, bh[s][ks]);
        }
    }
    float4* coef_s = (float4*)(sm + SC_CF);
    int*    u_s    = (int*)(sm + SC_U);
    int*    v_s    = (int*)(sm + SC_V);

    const int g4 = lane >> 2, t4 = lane & 3;

    for (int tile = blockIdx.x; tile < NTILES; tile += gridDim.x) {
        __syncthreads();
        const int eb = tile * 128;
        if (t < 128) {
            int e = eb + t;
            int u = ei[e], v = ei[NE + e];
            bool und = get_mask(mask, e, mode);
            float chr, chi, ctr, cti, dinv;
            if (und) { chr = 1.f;  chi = 0.f;   ctr = -1.f;  cti = 0.f;
                       dinv = (u == v) ? 0.f : RSQ2; }
            else     { chr = RSQ2; chi = -RSQ2; ctr = -RSQ2; cti = -RSQ2; dinv = RSQ2; }
            u_s[t] = u; v_s[t] = v;
            coef_s[t] = make_float4(dinv * chr, dinv * chi, dinv * ctr, dinv * cti);
        }
        for (int g = t; g < 2048; g += 256) {           // A tile (fp16)
            int row = g >> 4, k0 = (g & 15) * 8;
            float x[8];
            const float* ap = attr + (size_t)(eb + row) * 128 + k0;
            *(float4*)&x[0] = *(const float4*)ap;
            *(float4*)&x[4] = *(const float4*)(ap + 4);
            uint4 av; cvt8h(x, av);
            *(uint4*)(sm + SC_A + (row * 136 + k0) * 2) = av;
        }
        __syncthreads();

        // 4 mt interleaved: 8 independent accumulator chains
        float c[4][2][4];
        #pragma unroll
        for (int mt = 0; mt < 4; mt++)
            #pragma unroll
            for (int s = 0; s < 2; s++)
                c[mt][s][0] = c[mt][s][1] = c[mt][s][2] = c[mt][s][3] = 0.f;

        uint32_t acol0 = (uint32_t)((lane >> 4) << 4);
        #pragma unroll
        for (int ks = 0; ks < 8; ks++) {
            uint32_t a4[4][4];
            #pragma unroll
            for (int mt = 0; mt < 4; mt++) {
                uint32_t arow = (uint32_t)(wm * 64 + mt * 16 + (lane & 15)) * 272;
                ldsm4(sb + SC_A + arow + ks * 32 + acol0, a4[mt]);
            }
            #pragma unroll
            for (int mt = 0; mt < 4; mt++) {
                mma16816(c[mt][0], a4[mt], bh[0][ks]);
                mma16816(c[mt][1], a4[mt], bh[1][ks]);
            }
        }

        #pragma unroll
        for (int mt = 0; mt < 4; mt++) {
            #pragma unroll
            for (int s = 0; s < 2; s++) {
                int col = 16 * wn + 8 * s + 2 * t4;
                #pragma unroll
                for (int rr = 0; rr < 2; rr++) {
                    int el = wm * 64 + mt * 16 + g4 + rr * 8;
                    float re = c[mt][s][rr * 2], im = c[mt][s][rr * 2 + 1];
                    float4 cf = coef_s[el];
                    int u = u_s[el], v = v_s[el];
                    float hvx = cf.x * re - cf.y * im, hvy = cf.x * im + cf.y * re;
                    float hux = cf.z * re - cf.w * im, huy = cf.z * im + cf.w * re;
                    float pvx = __shfl_xor_sync(0xffffffffu, hvx, 1);
                    float pvy = __shfl_xor_sync(0xffffffffu, hvy, 1);
                    float pux = __shfl_xor_sync(0xffffffffu, hux, 1);
                    float puy = __shfl_xor_sync(0xffffffffu, huy, 1);
                    if (t4 & 1) red4(&g_h[(size_t)u * 64 + col - 2], pux, puy, hux, huy);
                    else        red4(&g_h[(size_t)v * 64 + col],     hvx, hvy, pvx, pvy);
                }
            }
        }
    }
}

// ---------------- gather: out = [y|attr]@Wcat^T + b  (y precomputed in g_y) ----------------
// smem: W[128][200]h (reused as A1 after B-frag load), A0[128][200]h, bias[128]f
// 256 threads, 2 CTAs/SM; warp w owns out cols [16w, 16w+16) (2 B strips in regs)
#define GA_W  0
#define GA_A0 51200
#define GA_BI 102400
#define GA_SMEM 102912

__global__ __launch_bounds__(256, 2)
void gather_kernel(const float* __restrict__ attr,
                   const float* __restrict__ W_out, const float* __restrict__ W_skip,
                   const float* __restrict__ b_skip, const float* __restrict__ bias,
                   float* __restrict__ out) {
    extern __shared__ char sm[];
    const uint32_t sb = s2u(sm);
    const int t = threadIdx.x, w = t >> 5, lane = t & 31;

    // stage Wcat [128 x 192] once: k<64 -> W_out, else W_skip (fp16)
    for (int g = t; g < 3072; g += 256) {
        int row = g / 24, k0 = (g % 24) * 8;
        float x[8];
        if (k0 < 64) {
            *(float4*)&x[0] = *(const float4*)(W_out + row * 64 + k0);
            *(float4*)&x[4] = *(const float4*)(W_out + row * 64 + k0 + 4);
        } else {
            *(float4*)&x[0] = *(const float4*)(W_skip + row * 128 + (k0 - 64));
            *(float4*)&x[4] = *(const float4*)(W_skip + row * 128 + (k0 - 64) + 4);
        }
        uint4 hv; cvt8h(x, hv);
        *(uint4*)(sm + GA_W + (row * 200 + k0) * 2) = hv;
    }
    if (t < 128) ((float*)(sm + GA_BI))[t] = b_skip[t] + bias[t];
    __syncthreads();

    // resident B fragments: warp owns out cols [16w, 16w+16) -> 2 strips
    uint32_t bh[2][12][2];
    #pragma unroll
    for (int s = 0; s < 2; s++) {
        uint32_t ro = (uint32_t)(16 * w + 8 * s + (lane & 7)) * 400;
        #pragma unroll
        for (int ks = 0; ks < 12; ks++) {
            uint32_t co = (uint32_t)(ks * 16 + (lane & 8)) * 2;
            ldsm2(sb + GA_W + ro + co, bh[s][ks]);
        }
    }
    const int g4 = lane >> 2, t4 = lane & 3;
    float2 b2[2];
    b2[0] = *(float2*)(sm + GA_BI + (16 * w + 2 * t4) * 4);
    b2[1] = *(float2*)(sm + GA_BI + (16 * w + 8 + 2 * t4) * 4);
    __syncthreads();   // B frags read -> W region reusable as A1

    const uint32_t abuf[2] = { sb + GA_A0, sb + GA_W };

    // ---- stage one tile: y copy (fp16, no math) + attr cvt ----
    auto stage = [&](int tile, int bi) {
        const int eb = tile * 128;
        char* buf = sm + (bi ? GA_W : GA_A0);
        for (int g = t; g < 1024; g += 256) {           // y -> k rows [0,64)
            int row = g >> 3, q = g & 7;                // q-th uint4 = 8 halves
            uint4 yv = *(const uint4*)&g_y[(size_t)(eb + row) * 32 + q * 4];
            *(uint4*)(buf + (row * 200 + q * 8) * 2) = yv;
        }
        for (int g = t; g < 2048; g += 256) {           // attr -> k rows [64,192)
            int row = g >> 4, k0 = (g & 15) * 8;
            float x[8];
            const float* ap = attr + (size_t)(eb + row) * 128 + k0;
            *(float4*)&x[0] = *(const float4*)ap;
            *(float4*)&x[4] = *(const float4*)(ap + 4);
            uint4 av; cvt8h(x, av);
            *(uint4*)(buf + (row * 200 + 64 + k0) * 2) = av;
        }
    };

    int tile = blockIdx.x;
    if (tile < NTILES) stage(tile, 0);
    __syncthreads();
    int ph = 0;
    for (; tile < NTILES; tile += gridDim.x) {
        int next = tile + gridDim.x;
        if (next < NTILES) stage(next, ph ^ 1);          // overlap with MMA below

        const int eb = tile * 128;
        #pragma unroll 1
        for (int mt = 0; mt < 8; mt++) {
            const int m0 = mt * 16;
            float c0[4] = {0.f, 0.f, 0.f, 0.f};
            float c1[4] = {0.f, 0.f, 0.f, 0.f};
            uint32_t arow  = (uint32_t)(m0 + (lane & 15)) * 400;
            uint32_t acol0 = (uint32_t)((lane >> 4) << 4);
            #pragma unroll
            for (int ks = 0; ks < 12; ks++) {
                uint32_t a4[4];
                ldsm4(abuf[ph] + arow + ks * 32 + acol0, a4);
                mma16816(c0, a4, bh[0][ks]);
                mma16816(c1, a4, bh[1][ks]);
            }
            int e0 = eb + m0 + g4;
            int ca = 16 * w + 2 * t4;
            *(float2*)&out[(size_t)e0 * 128 + ca] =
                make_float2(c0[0] + b2[0].x, c0[1] + b2[0].y);
            *(float2*)&out[(size_t)(e0 + 8) * 128 + ca] =
                make_float2(c0[2] + b2[0].x, c0[3] + b2[0].y);
            *(float2*)&out[(size_t)e0 * 128 + ca + 8] =
                make_float2(c1[0] + b2[1].x, c1[1] + b2[1].y);
            *(float2*)&out[(size_t)(e0 + 8) * 128 + ca + 8] =
                make_float2(c1[2] + b2[1].x, c1[3] + b2[1].y);
        }
        __syncthreads();
        ph ^= 1;
    }
}

extern "C" void kernel_launch(void* const* d_in, const int* in_sizes, int n_in,
                              void* d_out, int out_size) {
    const int*   edge_index = (const int*)  d_in[0];
    const void*  mask       =               d_in[1];
    const float* edge_attr  = (const float*)d_in[2];
    const float* W_in       = (const float*)d_in[3];
    const float* W_out      = (const float*)d_in[4];
    const float* W_skip     = (const float*)d_in[5];
    const float* b_skip     = (const float*)d_in[6];
    const float* bias       = (const float*)d_in[7];
    float*       out        = (float*)d_out;

    cudaFuncSetAttribute(scatter_kernel, cudaFuncAttributeMaxDynamicSharedMemorySize, SC_SMEM);
    cudaFuncSetAttribute(gather_kernel,  cudaFuncAttributeMaxDynamicSharedMemorySize, GA_SMEM);

    probe_mask_kernel<<<1, 256>>>((const unsigned char*)mask);
    zero_h_kernel<<<148, 256>>>();
    scatter_kernel<<<444, 256, SC_SMEM>>>(edge_index, mask, edge_attr, W_in);
    ybuild_kernel<<<1184, 256>>>(edge_index, mask);
    gather_kernel<<<296, 256, GA_SMEM>>>(edge_attr, W_out, W_skip, b_skip, bias, out);
}

// round 16
// speedup vs baseline: 1.2085x; 1.0322x over previous
#include <cuda_runtime.h>
#include <cuda_fp16.h>
#include <cstdint>

#define NE 800000
#define NN 50000
#define NTILES (NE/128)
#define RSQ2 0.70710678118654752440f

__device__ float    g_h[NN * 64];
__device__ uint32_t g_y[NE * 32];     // per-edge y, fp16x2 pairs (channels 2p,2p+1)
__device__ uint32_t g_ah[NE * 64];    // attr in fp16x2 (written by scatter staging)
__device__ int      g_mask_mode;

// ---------------- helpers ----------------
static __device__ __forceinline__ uint32_t s2u(const void* p) {
    uint32_t a;
    asm("{ .reg .u64 t; cvta.to.shared.u64 t, %1; cvt.u32.u64 %0, t; }" : "=r"(a) : "l"(p));
    return a;
}
static __device__ __forceinline__ void ldsm4(uint32_t a, uint32_t r[4]) {
    asm volatile("ldmatrix.sync.aligned.m8n8.x4.shared.b16 {%0,%1,%2,%3}, [%4];"
                 : "=r"(r[0]), "=r"(r[1]), "=r"(r[2]), "=r"(r[3]) : "r"(a));
}
static __device__ __forceinline__ void ldsm2(uint32_t a, uint32_t r[2]) {
    asm volatile("ldmatrix.sync.aligned.m8n8.x2.shared.b16 {%0,%1}, [%2];"
                 : "=r"(r[0]), "=r"(r[1]) : "r"(a));
}
static __device__ __forceinline__ void mma16816(float c[4], const uint32_t a[4],
                                                const uint32_t b[2]) {
    asm volatile("mma.sync.aligned.m16n8k16.row.col.f32.f16.f16.f32 "
                 "{%0,%1,%2,%3}, {%4,%5,%6,%7}, {%8,%9}, {%0,%1,%2,%3};"
                 : "+f"(c[0]), "+f"(c[1]), "+f"(c[2]), "+f"(c[3])
                 : "r"(a[0]), "r"(a[1]), "r"(a[2]), "r"(a[3]), "r"(b[0]), "r"(b[1]));
}
static __device__ __forceinline__ void red4(float* p, float a, float b, float c, float d) {
    asm volatile("red.global.add.v4.f32 [%0], {%1, %2, %3, %4};"
                 :: "l"(p), "f"(a), "f"(b), "f"(c), "f"(d) : "memory");
}
static __device__ __forceinline__ uint32_t f2h2(float a, float b) {
    __half2 h = __floats2half2_rn(a, b);
    return *(uint32_t*)&h;
}
static __device__ __forceinline__ void cvt8h(const float* x, uint4& o) {
    o = make_uint4(f2h2(x[0], x[1]), f2h2(x[2], x[3]),
                   f2h2(x[4], x[5]), f2h2(x[6], x[7]));
}

// ---------------- mask dtype ----------------
static __device__ __forceinline__ bool get_mask(const void* m, int e, int mode) {
    if (mode == 0) return ((const int*)m)[e] != 0;
    if (mode == 1) return ((const unsigned char*)m)[e] != 0;
    return ((const float*)m)[e] != 0.0f;
}
__global__ void probe_mask_kernel(const unsigned char* __restrict__ m) {
    __shared__ int flag[4];
    int t = threadIdx.x;
    if (t < 4) flag[t] = 0;
    __syncthreads();
    int any = 0;
    for (int i = t; i < 4096; i += 256) any |= (int)m[i];
    if (any) atomicOr(&flag[t & 3], 1);
    __syncthreads();
    if (t == 0) {
        int mode;
        if (flag[1] || (flag[0] && (flag[2] | flag[3]))) mode = 1;   // u8/bool
        else if (flag[2] | flag[3])                      mode = 2;   // f32
        else                                             mode = 0;   // i32
        g_mask_mode = mode;
    }
}

__global__ void zero_h_kernel() {
    float4* p = (float4*)g_h;
    const int n = NN * 64 / 4;
    for (int i = blockIdx.x * blockDim.x + threadIdx.x; i < n; i += gridDim.x * blockDim.x)
        p[i] = make_float4(0.f, 0.f, 0.f, 0.f);
}

// ---------------- y-build: y = dinv*(conj-phase . relu(h)) -> g_y (fp16) ----------------
__global__ __launch_bounds__(256)
void ybuild_kernel(const int* __restrict__ ei, const void* __restrict__ mask) {
    const int lane = threadIdx.x & 31;
    const int w    = (blockIdx.x * blockDim.x + threadIdx.x) >> 5;
    const int nw   = (gridDim.x * blockDim.x) >> 5;
    const int mode = g_mask_mode;
    for (int e = w; e < NE; e += nw) {
        int u = ei[e], v = ei[NE + e];                  // broadcast loads
        bool und = get_mask(mask, e, mode);
        float ar, ai, br, bi2, dinv = RSQ2;
        if (und) { ar = 1.f;  ai = 0.f;  br = -1.f;  bi2 = 0.f;
                   if (u == v) dinv = 0.f; }
        else     { ar = RSQ2; ai = RSQ2; br = -RSQ2; bi2 = RSQ2; }
        ar *= dinv; ai *= dinv; br *= dinv; bi2 *= dinv;
        float2 hv = *(const float2*)&g_h[(size_t)v * 64 + 2 * lane];
        float2 hu = *(const float2*)&g_h[(size_t)u * 64 + 2 * lane];
        hv.x = fmaxf(hv.x, 0.f); hv.y = fmaxf(hv.y, 0.f);  // fused ReLU
        hu.x = fmaxf(hu.x, 0.f); hu.y = fmaxf(hu.y, 0.f);
        float yr = ar * hv.x - ai * hv.y + br * hu.x - bi2 * hu.y;
        float yi = ar * hv.y + ai * hv.x + br * hu.y + bi2 * hu.x;
        g_y[(size_t)e * 32 + lane] = f2h2(yr, yi);
    }
}

// ---------------- scatter: z = (attr @ W_in^T)*dinv ; phase*z -> g_h ; attr->g_ah ----------------
// smem: W[64][136]h, A[128][136]h, coef f4[128], u[128], v[128]
// warp w: wm = w>>2 (M half, 64 rows = 4 mt), wn = w&3 (16-col group, 2 strips)
#define SC_W  0
#define SC_A  17408
#define SC_CF 52224
#define SC_U  54272
#define SC_V  54784
#define SC_SMEM 55296

__global__ __launch_bounds__(256, 3)
void scatter_kernel(const int* __restrict__ ei, const void* __restrict__ mask,
                    const float* __restrict__ attr, const float* __restrict__ W_in) {
    extern __shared__ char sm[];
    const uint32_t sb = s2u(sm);
    const int t = threadIdx.x, w = t >> 5, lane = t & 31;
    const int wm = w >> 2, wn = w & 3;
    const int mode = g_mask_mode;

    // stage W_in [64 x 128] once (fp16, padded rows of 136 halves)
    for (int g = t; g < 1024; g += 256) {
        int row = g >> 4, k0 = (g & 15) * 8;
        float x[8];
        *(float4*)&x[0] = *(const float4*)(W_in + row * 128 + k0);
        *(float4*)&x[4] = *(const float4*)(W_in + row * 128 + k0 + 4);
        uint4 hv; cvt8h(x, hv);
        *(uint4*)(sm + SC_W + (row * 136 + k0) * 2) = hv;
    }
    __syncthreads();

    // resident B fragments: warp owns hid cols [16wn, 16wn+16) -> 2 strips
    uint32_t bh[2][8][2];
    #pragma unroll
    for (int s = 0; s < 2; s++) {
        uint32_t ro = (uint32_t)(16 * wn + 8 * s + (lane & 7)) * 272;
        #pragma unroll
        for (int ks = 0; ks < 8; ks++) {
            uint32_t co = (uint32_t)(ks * 16 + (lane & 8)) * 2;
            ldsm2(sb + SC_W + ro + co, bh[s][ks]);
        }
    }
    float4* coef_s = (float4*)(sm + SC_CF);
    int*    u_s    = (int*)(sm + SC_U);
    int*    v_s    = (int*)(sm + SC_V);

    const int g4 = lane >> 2, t4 = lane & 3;

    for (int tile = blockIdx.x; tile < NTILES; tile += gridDim.x) {
        __syncthreads();
        const int eb = tile * 128;
        if (t < 128) {
            int e = eb + t;
            int u = ei[e], v = ei[NE + e];
            bool und = get_mask(mask, e, mode);
            float chr, chi, ctr, cti, dinv;
            if (und) { chr = 1.f;  chi = 0.f;   ctr = -1.f;  cti = 0.f;
                       dinv = (u == v) ? 0.f : RSQ2; }
            else     { chr = RSQ2; chi = -RSQ2; ctr = -RSQ2; cti = -RSQ2; dinv = RSQ2; }
            u_s[t] = u; v_s[t] = v;
            coef_s[t] = make_float4(dinv * chr, dinv * chi, dinv * ctr, dinv * cti);
        }
        for (int g = t; g < 2048; g += 256) {           // A tile (fp16) + dump to g_ah
            int row = g >> 4, k0 = (g & 15) * 8;
            float x[8];
            const float* ap = attr + (size_t)(eb + row) * 128 + k0;
            *(float4*)&x[0] = *(const float4*)ap;
            *(float4*)&x[4] = *(const float4*)(ap + 4);
            uint4 av; cvt8h(x, av);
            *(uint4*)(sm + SC_A + (row * 136 + k0) * 2) = av;
            *(uint4*)&g_ah[(size_t)(eb + row) * 64 + (k0 >> 1)] = av;
        }
        __syncthreads();

        // 4 mt interleaved: 8 independent accumulator chains
        float c[4][2][4];
        #pragma unroll
        for (int mt = 0; mt < 4; mt++)
            #pragma unroll
            for (int s = 0; s < 2; s++)
                c[mt][s][0] = c[mt][s][1] = c[mt][s][2] = c[mt][s][3] = 0.f;

        uint32_t acol0 = (uint32_t)((lane >> 4) << 4);
        #pragma unroll
        for (int ks = 0; ks < 8; ks++) {
            uint32_t a4[4][4];
            #pragma unroll
            for (int mt = 0; mt < 4; mt++) {
                uint32_t arow = (uint32_t)(wm * 64 + mt * 16 + (lane & 15)) * 272;
                ldsm4(sb + SC_A + arow + ks * 32 + acol0, a4[mt]);
            }
            #pragma unroll
            for (int mt = 0; mt < 4; mt++) {
                mma16816(c[mt][0], a4[mt], bh[0][ks]);
                mma16816(c[mt][1], a4[mt], bh[1][ks]);
            }
        }

        #pragma unroll
        for (int mt = 0; mt < 4; mt++) {
            #pragma unroll
            for (int s = 0; s < 2; s++) {
                int col = 16 * wn + 8 * s + 2 * t4;
                #pragma unroll
                for (int rr = 0; rr < 2; rr++) {
                    int el = wm * 64 + mt * 16 + g4 + rr * 8;
                    float re = c[mt][s][rr * 2], im = c[mt][s][rr * 2 + 1];
                    float4 cf = coef_s[el];
                    int u = u_s[el], v = v_s[el];
                    float hvx = cf.x * re - cf.y * im, hvy = cf.x * im + cf.y * re;
                    float hux = cf.z * re - cf.w * im, huy = cf.z * im + cf.w * re;
                    float pvx = __shfl_xor_sync(0xffffffffu, hvx, 1);
                    float pvy = __shfl_xor_sync(0xffffffffu, hvy, 1);
                    float pux = __shfl_xor_sync(0xffffffffu, hux, 1);
                    float puy = __shfl_xor_sync(0xffffffffu, huy, 1);
                    if (t4 & 1) red4(&g_h[(size_t)u * 64 + col - 2], pux, puy, hux, huy);
                    else        red4(&g_h[(size_t)v * 64 + col],     hvx, hvy, pvx, pvy);
                }
            }
        }
    }
}

// ---------------- gather: out = [y|attr]@Wcat^T + b  (y in g_y, attr fp16 in g_ah) ----------------
// smem: W[128][200]h (reused as A1 after B-frag load), A0[128][200]h, bias[128]f
// 256 threads, 2 CTAs/SM; warp w owns out cols [16w, 16w+16) (2 B strips in regs)
#define GA_W  0
#define GA_A0 51200
#define GA_BI 102400
#define GA_SMEM 102912

__global__ __launch_bounds__(256, 2)
void gather_kernel(const float* __restrict__ W_out, const float* __restrict__ W_skip,
                   const float* __restrict__ b_skip, const float* __restrict__ bias,
                   float* __restrict__ out) {
    extern __shared__ char sm[];
    const uint32_t sb = s2u(sm);
    const int t = threadIdx.x, w = t >> 5, lane = t & 31;

    // stage Wcat [128 x 192] once: k<64 -> W_out, else W_skip (fp16)
    for (int g = t; g < 3072; g += 256) {
        int row = g / 24, k0 = (g % 24) * 8;
        float x[8];
        if (k0 < 64) {
            *(float4*)&x[0] = *(const float4*)(W_out + row * 64 + k0);
            *(float4*)&x[4] = *(const float4*)(W_out + row * 64 + k0 + 4);
        } else {
            *(float4*)&x[0] = *(const float4*)(W_skip + row * 128 + (k0 - 64));
            *(float4*)&x[4] = *(const float4*)(W_skip + row * 128 + (k0 - 64) + 4);
        }
        uint4 hv; cvt8h(x, hv);
        *(uint4*)(sm + GA_W + (row * 200 + k0) * 2) = hv;
    }
    if (t < 128) ((float*)(sm + GA_BI))[t] = b_skip[t] + bias[t];
    __syncthreads();

    // resident B fragments: warp owns out cols [16w, 16w+16) -> 2 strips
    uint32_t bh[2][12][2];
    #pragma unroll
    for (int s = 0; s < 2; s++) {
        uint32_t ro = (uint32_t)(16 * w + 8 * s + (lane & 7)) * 400;
        #pragma unroll
        for (int ks = 0; ks < 12; ks++) {
            uint32_t co = (uint32_t)(ks * 16 + (lane & 8)) * 2;
            ldsm2(sb + GA_W + ro + co, bh[s][ks]);
        }
    }
    const int g4 = lane >> 2, t4 = lane & 3;
    float2 b2[2];
    b2[0] = *(float2*)(sm + GA_BI + (16 * w + 2 * t4) * 4);
    b2[1] = *(float2*)(sm + GA_BI + (16 * w + 8 + 2 * t4) * 4);
    __syncthreads();   // B frags read -> W region reusable as A1

    const uint32_t abuf[2] = { sb + GA_A0, sb + GA_W };

    // ---- stage one tile: pure 16B copies (y + pre-converted attr) ----
    auto stage = [&](int tile, int bi) {
        const int eb = tile * 128;
        char* buf = sm + (bi ? GA_W : GA_A0);
        for (int g = t; g < 1024; g += 256) {           // y -> k rows [0,64): 8 uint4/row
            int row = g >> 3, q = g & 7;
            uint4 yv = *(const uint4*)&g_y[(size_t)(eb + row) * 32 + q * 4];
            *(uint4*)(buf + (row * 200 + q * 8) * 2) = yv;
        }
        for (int g = t; g < 2048; g += 256) {           // attr -> k rows [64,192): 16 uint4/row
            int row = g >> 4, q = g & 15;
            uint4 av = *(const uint4*)&g_ah[(size_t)(eb + row) * 64 + q * 4];
            *(uint4*)(buf + (row * 200 + 64 + q * 8) * 2) = av;
        }
    };

    int tile = blockIdx.x;
    if (tile < NTILES) stage(tile, 0);
    __syncthreads();
    int ph = 0;
    for (; tile < NTILES; tile += gridDim.x) {
        int next = tile + gridDim.x;
        if (next < NTILES) stage(next, ph ^ 1);          // overlap with MMA below

        const int eb = tile * 128;
        #pragma unroll 1
        for (int mt = 0; mt < 8; mt++) {
            const int m0 = mt * 16;
            float c0[4] = {0.f, 0.f, 0.f, 0.f};
            float c1[4] = {0.f, 0.f, 0.f, 0.f};
            uint32_t arow  = (uint32_t)(m0 + (lane & 15)) * 400;
            uint32_t acol0 = (uint32_t)((lane >> 4) << 4);
            #pragma unroll
            for (int ks = 0; ks < 12; ks++) {
                uint32_t a4[4];
                ldsm4(abuf[ph] + arow + ks * 32 + acol0, a4);
                mma16816(c0, a4, bh[0][ks]);
                mma16816(c1, a4, bh[1][ks]);
            }
            int e0 = eb + m0 + g4;
            int ca = 16 * w + 2 * t4;
            *(float2*)&out[(size_t)e0 * 128 + ca] =
                make_float2(c0[0] + b2[0].x, c0[1] + b2[0].y);
            *(float2*)&out[(size_t)(e0 + 8) * 128 + ca] =
                make_float2(c0[2] + b2[0].x, c0[3] + b2[0].y);
            *(float2*)&out[(size_t)e0 * 128 + ca + 8] =
                make_float2(c1[0] + b2[1].x, c1[1] + b2[1].y);
            *(float2*)&out[(size_t)(e0 + 8) * 128 + ca + 8] =
                make_float2(c1[2] + b2[1].x, c1[3] + b2[1].y);
        }
        __syncthreads();
        ph ^= 1;
    }
}

extern "C" void kernel_launch(void* const* d_in, const int* in_sizes, int n_in,
                              void* d_out, int out_size) {
    const int*   edge_index = (const int*)  d_in[0];
    const void*  mask       =               d_in[1];
    const float* edge_attr  = (const float*)d_in[2];
    const float* W_in       = (const float*)d_in[3];
    const float* W_out      = (const float*)d_in[4];
    const float* W_skip     = (const float*)d_in[5];
    const float* b_skip     = (const float*)d_in[6];
    const float* bias       = (const float*)d_in[7];
    float*       out        = (float*)d_out;

    cudaFuncSetAttribute(scatter_kernel, cudaFuncAttributeMaxDynamicSharedMemorySize, SC_SMEM);
    cudaFuncSetAttribute(gather_kernel,  cudaFuncAttributeMaxDynamicSharedMemorySize, GA_SMEM);

    probe_mask_kernel<<<1, 256>>>((const unsigned char*)mask);
    zero_h_kernel<<<148, 256>>>();
    scatter_kernel<<<444, 256, SC_SMEM>>>(edge_index, mask, edge_attr, W_in);
    ybuild_kernel<<<1184, 256>>>(edge_index, mask);
    gather_kernel<<<296, 256, GA_SMEM>>>(W_out, W_skip, b_skip, bias, out);
}